// round 12
// baseline (speedup 1.0000x reference)
#include <cuda_runtime.h>

// Weighted AUC via binned rank statistic.
//   area = sum_{neg j} w_j * (pos weight above j);  AUC = area / (Wp * Wn)
// NBINS=1024: predicted rel_err ~6e-7 (measured 4.4e-7 @2048; threshold 1e-3).
//
// Pipeline (2 launches):
//   hist_kernel : 8 KB smem histogram per CTA, TMA bulk add-reduce into g_red.
//                 Halved flush volume (8 MB) halves the L2 reduce-ALU drain
//                 exposed at wave end (round-11 analysis).
//   auc_kernel  : reduce NG copies + warp-parallel scan + finalize; re-zeroes
//                 g_red for the next replay (zeroed at module load initially).

#define N_TASKS 16
#define N_EX    2097152
#define NBINS   1024
#define LSHIFT  10                // label class offset shift: (int)label << 10
#define HBINS   (2 * NBINS)       // [neg | pos] halves = 2048 floats = 8 KB
#define NCHUNK  64                // hist CTAs per task
#define NG      4                 // accumulation groups (contention spreading)
#define HT      256               // hist kernel threads
#define AT      256               // auc kernel threads (8 warps)
#define NW      (AT / 32)         // 8 warps
#define ELEMS_PER_CTA (N_EX / NCHUNK)          // 32768
#define VECS_PER_THR  (ELEMS_PER_CTA / 4 / HT) // 32
#define COLS4   (HBINS / 4)       // 512 float4 columns

// Accumulated partials: [task][group][HBINS] (512 KB). Zero at module load;
// re-zeroed by auc_kernel each run.
__device__ float g_red[(size_t)N_TASKS * NG * HBINS];

__global__ void __launch_bounds__(HT, 8) hist_kernel(const float* __restrict__ pred,
                                                     const float* __restrict__ lab,
                                                     const float* __restrict__ wt) {
    __shared__ float sh[HBINS];  // 8 KB -> thread-limited 8 CTAs/SM, 64 warps

    const int chunk = blockIdx.x;
    const int task  = blockIdx.y;
    const int tid   = threadIdx.x;

    float4* sh4 = reinterpret_cast<float4*>(sh);
    const float4 z = make_float4(0.f, 0.f, 0.f, 0.f);
#pragma unroll
    for (int i = tid; i < COLS4; i += HT) sh4[i] = z;
    __syncthreads();

    const size_t base = (size_t)task * N_EX + (size_t)chunk * ELEMS_PER_CTA;
    const float4* __restrict__ p4 = reinterpret_cast<const float4*>(pred + base);
    const float4* __restrict__ l4 = reinterpret_cast<const float4*>(lab  + base);
    const float4* __restrict__ w4 = reinterpret_cast<const float4*>(wt   + base);

#pragma unroll 2
    for (int it = 0; it < VECS_PER_THR; it++) {
        const int i = tid + it * HT;
        // Streaming loads (evict-first): read-once data.
        const float4 p = __ldcs(p4 + i);
        const float4 l = __ldcs(l4 + i);
        const float4 w = __ldcs(w4 + i);

        int b0 = (int)(p.x * (float)NBINS); b0 = b0 > NBINS - 1 ? NBINS - 1 : b0;
        int b1 = (int)(p.y * (float)NBINS); b1 = b1 > NBINS - 1 ? NBINS - 1 : b1;
        int b2 = (int)(p.z * (float)NBINS); b2 = b2 > NBINS - 1 ? NBINS - 1 : b2;
        int b3 = (int)(p.w * (float)NBINS); b3 = b3 > NBINS - 1 ? NBINS - 1 : b3;

        // labels are exact 0.0f / 1.0f
        atomicAdd(&sh[b0 + ((int)l.x << LSHIFT)], w.x);
        atomicAdd(&sh[b1 + ((int)l.y << LSHIFT)], w.y);
        atomicAdd(&sh[b2 + ((int)l.z << LSHIFT)], w.z);
        atomicAdd(&sh[b3 + ((int)l.w << LSHIFT)], w.w);
    }
    __syncthreads();

    // TMA bulk add-reduce of the whole 8 KB histogram into this task's
    // group copy at L2.
    if (tid == 0) {
        const int grp = chunk & (NG - 1);
        float* dst = g_red + ((size_t)task * NG + grp) * HBINS;
        unsigned smem_u32 = (unsigned)__cvta_generic_to_shared(sh);
        asm volatile("fence.proxy.async.shared::cta;" ::: "memory");
        asm volatile(
            "cp.reduce.async.bulk.global.shared::cta.bulk_group.add.f32 "
            "[%0], [%1], %2;"
            :: "l"(dst), "r"(smem_u32), "r"((int)(HBINS * sizeof(float)))
            : "memory");
        asm volatile("cp.async.bulk.commit_group;" ::: "memory");
        asm volatile("cp.async.bulk.wait_group.read 0;" ::: "memory");
    }
}

// Reduce NG copies + parallel scan + finalize; re-zero g_red for next replay.
__global__ void __launch_bounds__(AT) auc_kernel(float* __restrict__ out) {
    __shared__ float sh[HBINS];              // reduced: [neg | pos], 8 KB
    __shared__ float s_warp[NW];
    __shared__ float s_wn_warp[NW];
    __shared__ float s_num_warp[NW];
    __shared__ float s_wpos;

    const int task = blockIdx.x;
    const int t    = threadIdx.x;
    const int lane = t & 31;
    const int wid  = t >> 5;

    // ---- reduce NG=4 group copies; re-zero in place (same-thread order) ----
    {
        float4* __restrict__ src =
            reinterpret_cast<float4*>(g_red + (size_t)task * NG * HBINS);
        const float4 z = make_float4(0.f, 0.f, 0.f, 0.f);
#pragma unroll
        for (int c = 0; c < COLS4 / AT; c++) {       // 2 columns per thread
            const int col = t + c * AT;
            float4 s = z;
#pragma unroll
            for (int g = 0; g < NG; g++) {
                const float4 v = src[col + g * COLS4];
                s.x += v.x; s.y += v.y; s.z += v.z; s.w += v.w;
            }
#pragma unroll
            for (int g = 0; g < NG; g++) src[col + g * COLS4] = z;
            reinterpret_cast<float4*>(sh)[col] = s;
        }
    }
    __syncthreads();

    // ---- per-thread sums over PB=4 bins, descending prediction order ----
    const int PB = NBINS / AT;  // 4
    float swp = 0.0f, swn = 0.0f;
#pragma unroll
    for (int k = 0; k < PB; k++) {
        const int bin = NBINS - 1 - (t * PB + k);
        swp += sh[NBINS + bin];
        swn += sh[bin];
    }

    // ---- warp-parallel exclusive prefix of swp across 256 threads ----
    float incl = swp;
#pragma unroll
    for (int d = 1; d < 32; d <<= 1) {
        const float v = __shfl_up_sync(0xffffffffu, incl, d);
        if (lane >= d) incl += v;
    }
    if (lane == 31) s_warp[wid] = incl;          // warp totals
    __syncthreads();
    if (wid == 0) {
        float wv = (lane < NW) ? s_warp[lane] : 0.0f;
        float wincl = wv;
#pragma unroll
        for (int d = 1; d < NW; d <<= 1) {
            const float v = __shfl_up_sync(0xffffffffu, wincl, d);
            if (lane >= d) wincl += v;
        }
        if (lane < NW) s_warp[lane] = wincl - wv;    // exclusive warp offsets
        if (lane == NW - 1) s_wpos = wincl;          // total W_pos
    }
    __syncthreads();
    const float pref = s_warp[wid] + (incl - swp);   // exclusive prefix for t

    // ---- numerator for this thread's bins ----
    float cum = pref;    // positive weight strictly above these bins
    float num = 0.0f;
#pragma unroll
    for (int k = 0; k < PB; k++) {
        const int bin = NBINS - 1 - (t * PB + k);
        const float wp = sh[NBINS + bin];
        const float wn = sh[bin];
        num += wn * (cum + 0.5f * wp);
        cum += wp;
    }

    // ---- tree-reduce num and swn ----
#pragma unroll
    for (int d = 16; d >= 1; d >>= 1) {
        num += __shfl_down_sync(0xffffffffu, num, d);
        swn += __shfl_down_sync(0xffffffffu, swn, d);
    }
    if (lane == 0) { s_num_warp[wid] = num; s_wn_warp[wid] = swn; }
    __syncthreads();

    if (t == 0) {
        float tot = 0.0f, Wn = 0.0f;
#pragma unroll
        for (int i = 0; i < NW; i++) { tot += s_num_warp[i]; Wn += s_wn_warp[i]; }
        const float Wp = s_wpos;
        const double denom = (double)Wp * (double)Wn;
        out[task] = (denom == 0.0) ? 0.5f : (float)((double)tot / denom);
    }
}

extern "C" void kernel_launch(void* const* d_in, const int* in_sizes, int n_in,
                              void* d_out, int out_size) {
    // The three big float arrays in metadata order: predictions, labels, weights.
    const float* pred = nullptr;
    const float* lab  = nullptr;
    const float* wt   = nullptr;
    int found = 0;
    for (int i = 0; i < n_in; i++) {
        if (in_sizes[i] == N_TASKS * N_EX) {
            if      (found == 0) pred = (const float*)d_in[i];
            else if (found == 1) lab  = (const float*)d_in[i];
            else if (found == 2) wt   = (const float*)d_in[i];
            found++;
        }
    }

    dim3 grid(NCHUNK, N_TASKS);  // 1024 CTAs, 8/SM -> one full wave
    hist_kernel<<<grid, HT>>>(pred, lab, wt);
    auc_kernel<<<N_TASKS, AT>>>((float*)d_out);
}

// round 13
// speedup vs baseline: 1.0338x; 1.0338x over previous
#include <cuda_runtime.h>

// Weighted AUC via binned rank statistic.
//   area = sum_{neg j} w_j * (pos weight above j);  AUC = area / (Wp * Wn)
// NBINS=1024: predicted rel_err ~6e-7 (measured 4.4e-7 @2048; threshold 1e-3).
//
// Pipeline (2 launches):
//   hist_kernel : 8 KB smem histogram per CTA, TMA bulk add-reduce into g_red.
//                 Halved flush volume (8 MB) halves the L2 reduce-ALU drain
//                 exposed at wave end (round-11 analysis).
//   auc_kernel  : reduce NG copies + warp-parallel scan + finalize; re-zeroes
//                 g_red for the next replay (zeroed at module load initially).

#define N_TASKS 16
#define N_EX    2097152
#define NBINS   1024
#define LSHIFT  10                // label class offset shift: (int)label << 10
#define HBINS   (2 * NBINS)       // [neg | pos] halves = 2048 floats = 8 KB
#define NCHUNK  64                // hist CTAs per task
#define NG      4                 // accumulation groups (contention spreading)
#define HT      256               // hist kernel threads
#define AT      256               // auc kernel threads (8 warps)
#define NW      (AT / 32)         // 8 warps
#define ELEMS_PER_CTA (N_EX / NCHUNK)          // 32768
#define VECS_PER_THR  (ELEMS_PER_CTA / 4 / HT) // 32
#define COLS4   (HBINS / 4)       // 512 float4 columns

// Accumulated partials: [task][group][HBINS] (512 KB). Zero at module load;
// re-zeroed by auc_kernel each run.
__device__ float g_red[(size_t)N_TASKS * NG * HBINS];

__global__ void __launch_bounds__(HT, 8) hist_kernel(const float* __restrict__ pred,
                                                     const float* __restrict__ lab,
                                                     const float* __restrict__ wt) {
    __shared__ float sh[HBINS];  // 8 KB -> thread-limited 8 CTAs/SM, 64 warps

    const int chunk = blockIdx.x;
    const int task  = blockIdx.y;
    const int tid   = threadIdx.x;

    float4* sh4 = reinterpret_cast<float4*>(sh);
    const float4 z = make_float4(0.f, 0.f, 0.f, 0.f);
#pragma unroll
    for (int i = tid; i < COLS4; i += HT) sh4[i] = z;
    __syncthreads();

    const size_t base = (size_t)task * N_EX + (size_t)chunk * ELEMS_PER_CTA;
    const float4* __restrict__ p4 = reinterpret_cast<const float4*>(pred + base);
    const float4* __restrict__ l4 = reinterpret_cast<const float4*>(lab  + base);
    const float4* __restrict__ w4 = reinterpret_cast<const float4*>(wt   + base);

#pragma unroll 2
    for (int it = 0; it < VECS_PER_THR; it++) {
        const int i = tid + it * HT;
        // Streaming loads (evict-first): read-once data.
        const float4 p = __ldcs(p4 + i);
        const float4 l = __ldcs(l4 + i);
        const float4 w = __ldcs(w4 + i);

        int b0 = (int)(p.x * (float)NBINS); b0 = b0 > NBINS - 1 ? NBINS - 1 : b0;
        int b1 = (int)(p.y * (float)NBINS); b1 = b1 > NBINS - 1 ? NBINS - 1 : b1;
        int b2 = (int)(p.z * (float)NBINS); b2 = b2 > NBINS - 1 ? NBINS - 1 : b2;
        int b3 = (int)(p.w * (float)NBINS); b3 = b3 > NBINS - 1 ? NBINS - 1 : b3;

        // labels are exact 0.0f / 1.0f
        atomicAdd(&sh[b0 + ((int)l.x << LSHIFT)], w.x);
        atomicAdd(&sh[b1 + ((int)l.y << LSHIFT)], w.y);
        atomicAdd(&sh[b2 + ((int)l.z << LSHIFT)], w.z);
        atomicAdd(&sh[b3 + ((int)l.w << LSHIFT)], w.w);
    }
    __syncthreads();

    // TMA bulk add-reduce of the whole 8 KB histogram into this task's
    // group copy at L2.
    if (tid == 0) {
        const int grp = chunk & (NG - 1);
        float* dst = g_red + ((size_t)task * NG + grp) * HBINS;
        unsigned smem_u32 = (unsigned)__cvta_generic_to_shared(sh);
        asm volatile("fence.proxy.async.shared::cta;" ::: "memory");
        asm volatile(
            "cp.reduce.async.bulk.global.shared::cta.bulk_group.add.f32 "
            "[%0], [%1], %2;"
            :: "l"(dst), "r"(smem_u32), "r"((int)(HBINS * sizeof(float)))
            : "memory");
        asm volatile("cp.async.bulk.commit_group;" ::: "memory");
        asm volatile("cp.async.bulk.wait_group.read 0;" ::: "memory");
    }
}

// Reduce NG copies + parallel scan + finalize; re-zero g_red for next replay.
__global__ void __launch_bounds__(AT) auc_kernel(float* __restrict__ out) {
    __shared__ float sh[HBINS];              // reduced: [neg | pos], 8 KB
    __shared__ float s_warp[NW];
    __shared__ float s_wn_warp[NW];
    __shared__ float s_num_warp[NW];
    __shared__ float s_wpos;

    const int task = blockIdx.x;
    const int t    = threadIdx.x;
    const int lane = t & 31;
    const int wid  = t >> 5;

    // ---- reduce NG=4 group copies; re-zero in place (same-thread order) ----
    {
        float4* __restrict__ src =
            reinterpret_cast<float4*>(g_red + (size_t)task * NG * HBINS);
        const float4 z = make_float4(0.f, 0.f, 0.f, 0.f);
#pragma unroll
        for (int c = 0; c < COLS4 / AT; c++) {       // 2 columns per thread
            const int col = t + c * AT;
            float4 s = z;
#pragma unroll
            for (int g = 0; g < NG; g++) {
                const float4 v = src[col + g * COLS4];
                s.x += v.x; s.y += v.y; s.z += v.z; s.w += v.w;
            }
#pragma unroll
            for (int g = 0; g < NG; g++) src[col + g * COLS4] = z;
            reinterpret_cast<float4*>(sh)[col] = s;
        }
    }
    __syncthreads();

    // ---- per-thread sums over PB=4 bins, descending prediction order ----
    const int PB = NBINS / AT;  // 4
    float swp = 0.0f, swn = 0.0f;
#pragma unroll
    for (int k = 0; k < PB; k++) {
        const int bin = NBINS - 1 - (t * PB + k);
        swp += sh[NBINS + bin];
        swn += sh[bin];
    }

    // ---- warp-parallel exclusive prefix of swp across 256 threads ----
    float incl = swp;
#pragma unroll
    for (int d = 1; d < 32; d <<= 1) {
        const float v = __shfl_up_sync(0xffffffffu, incl, d);
        if (lane >= d) incl += v;
    }
    if (lane == 31) s_warp[wid] = incl;          // warp totals
    __syncthreads();
    if (wid == 0) {
        float wv = (lane < NW) ? s_warp[lane] : 0.0f;
        float wincl = wv;
#pragma unroll
        for (int d = 1; d < NW; d <<= 1) {
            const float v = __shfl_up_sync(0xffffffffu, wincl, d);
            if (lane >= d) wincl += v;
        }
        if (lane < NW) s_warp[lane] = wincl - wv;    // exclusive warp offsets
        if (lane == NW - 1) s_wpos = wincl;          // total W_pos
    }
    __syncthreads();
    const float pref = s_warp[wid] + (incl - swp);   // exclusive prefix for t

    // ---- numerator for this thread's bins ----
    float cum = pref;    // positive weight strictly above these bins
    float num = 0.0f;
#pragma unroll
    for (int k = 0; k < PB; k++) {
        const int bin = NBINS - 1 - (t * PB + k);
        const float wp = sh[NBINS + bin];
        const float wn = sh[bin];
        num += wn * (cum + 0.5f * wp);
        cum += wp;
    }

    // ---- tree-reduce num and swn ----
#pragma unroll
    for (int d = 16; d >= 1; d >>= 1) {
        num += __shfl_down_sync(0xffffffffu, num, d);
        swn += __shfl_down_sync(0xffffffffu, swn, d);
    }
    if (lane == 0) { s_num_warp[wid] = num; s_wn_warp[wid] = swn; }
    __syncthreads();

    if (t == 0) {
        float tot = 0.0f, Wn = 0.0f;
#pragma unroll
        for (int i = 0; i < NW; i++) { tot += s_num_warp[i]; Wn += s_wn_warp[i]; }
        const float Wp = s_wpos;
        const double denom = (double)Wp * (double)Wn;
        out[task] = (denom == 0.0) ? 0.5f : (float)((double)tot / denom);
    }
}

extern "C" void kernel_launch(void* const* d_in, const int* in_sizes, int n_in,
                              void* d_out, int out_size) {
    // The three big float arrays in metadata order: predictions, labels, weights.
    const float* pred = nullptr;
    const float* lab  = nullptr;
    const float* wt   = nullptr;
    int found = 0;
    for (int i = 0; i < n_in; i++) {
        if (in_sizes[i] == N_TASKS * N_EX) {
            if      (found == 0) pred = (const float*)d_in[i];
            else if (found == 1) lab  = (const float*)d_in[i];
            else if (found == 2) wt   = (const float*)d_in[i];
            found++;
        }
    }

    dim3 grid(NCHUNK, N_TASKS);  // 1024 CTAs, 8/SM -> one full wave
    hist_kernel<<<grid, HT>>>(pred, lab, wt);
    auc_kernel<<<N_TASKS, AT>>>((float*)d_out);
}

// round 14
// speedup vs baseline: 1.0648x; 1.0301x over previous
#include <cuda_runtime.h>

// Weighted AUC via binned rank statistic.
//   area = sum_{neg j} w_j * (pos weight above j);  AUC = area / (Wp * Wn)
//
// Round-14 key idea: DECOUPLE atomic resolution from flush resolution.
//   - smem histogram at 2048 bins/class (best measured smem-atomic config)
//   - fold 4:1 to 512 bins/class before the TMA flush (cheapest L2 drain)
// Folding is exactly equivalent to direct 512-binning (floor(p*2048)>>2 ==
// floor(p*512)), so rel_err ~1.5e-6 as measured in round 8 (threshold 1e-3).

#define N_TASKS 16
#define N_EX    2097152
#define NBINS   2048              // smem atomic bins per class
#define LSHIFT  11                // label class offset shift: (int)label << 11
#define HBINS   (2 * NBINS)       // smem histogram: 4096 floats = 16 KB
#define FOLD    4                 // fold factor at flush
#define FB      (NBINS / FOLD)    // 512 flushed bins per class
#define FHB     (2 * FB)          // 1024 flushed floats = 4 KB
#define NCHUNK  64                // hist CTAs per task
#define NG      4                 // accumulation groups (contention spreading)
#define HT      256               // hist kernel threads
#define AT      256               // auc kernel threads (8 warps)
#define NW      (AT / 32)         // 8 warps
#define ELEMS_PER_CTA (N_EX / NCHUNK)          // 32768
#define VECS_PER_THR  (ELEMS_PER_CTA / 4 / HT) // 32
#define COLS4   (FHB / 4)         // 256 float4 columns in flushed histogram

// Accumulated folded partials: [task][group][FHB] (256 KB). Zero at module
// load; re-zeroed by auc_kernel each run.
__device__ float g_red[(size_t)N_TASKS * NG * FHB];

__global__ void __launch_bounds__(HT, 8) hist_kernel(const float* __restrict__ pred,
                                                     const float* __restrict__ lab,
                                                     const float* __restrict__ wt) {
    __shared__ float sh[HBINS];  // 16 KB -> 8 CTAs/SM, 64 warps

    const int chunk = blockIdx.x;
    const int task  = blockIdx.y;
    const int tid   = threadIdx.x;

    float4* sh4 = reinterpret_cast<float4*>(sh);
    const float4 z = make_float4(0.f, 0.f, 0.f, 0.f);
#pragma unroll
    for (int i = tid; i < HBINS / 4; i += HT) sh4[i] = z;
    __syncthreads();

    const size_t base = (size_t)task * N_EX + (size_t)chunk * ELEMS_PER_CTA;
    const float4* __restrict__ p4 = reinterpret_cast<const float4*>(pred + base);
    const float4* __restrict__ l4 = reinterpret_cast<const float4*>(lab  + base);
    const float4* __restrict__ w4 = reinterpret_cast<const float4*>(wt   + base);

#pragma unroll 2
    for (int it = 0; it < VECS_PER_THR; it++) {
        const int i = tid + it * HT;
        // Streaming loads (evict-first): read-once data.
        const float4 p = __ldcs(p4 + i);
        const float4 l = __ldcs(l4 + i);
        const float4 w = __ldcs(w4 + i);

        int b0 = (int)(p.x * (float)NBINS); b0 = b0 > NBINS - 1 ? NBINS - 1 : b0;
        int b1 = (int)(p.y * (float)NBINS); b1 = b1 > NBINS - 1 ? NBINS - 1 : b1;
        int b2 = (int)(p.z * (float)NBINS); b2 = b2 > NBINS - 1 ? NBINS - 1 : b2;
        int b3 = (int)(p.w * (float)NBINS); b3 = b3 > NBINS - 1 ? NBINS - 1 : b3;

        // labels are exact 0.0f / 1.0f
        atomicAdd(&sh[b0 + ((int)l.x << LSHIFT)], w.x);
        atomicAdd(&sh[b1 + ((int)l.y << LSHIFT)], w.y);
        atomicAdd(&sh[b2 + ((int)l.z << LSHIFT)], w.z);
        atomicAdd(&sh[b3 + ((int)l.w << LSHIFT)], w.w);
    }
    __syncthreads();

    // ---- fold 4:1 (2048 -> 512 bins per class) into registers, then pack
    //      into sh[0..FHB). Exactly equivalent to direct 512-binning. ----
    float fold[FHB / HT];  // 4 outputs per thread
#pragma unroll
    for (int o = 0; o < FHB / HT; o++) {
        const int j = tid + o * HT;        // 0..1023: packed [neg(512)|pos(512)]
        const int c = j >> 9;              // class
        const int b = j & (FB - 1);        // folded bin
        const int src = c * NBINS + b * FOLD;
        fold[o] = (sh[src] + sh[src + 1]) + (sh[src + 2] + sh[src + 3]);
    }
    __syncthreads();
#pragma unroll
    for (int o = 0; o < FHB / HT; o++) sh[tid + o * HT] = fold[o];
    __syncthreads();

    // TMA bulk add-reduce of the folded 4 KB histogram into this task's
    // group copy at L2 (4x less drain than flushing all 2048 bins).
    if (tid == 0) {
        const int grp = chunk & (NG - 1);
        float* dst = g_red + ((size_t)task * NG + grp) * FHB;
        unsigned smem_u32 = (unsigned)__cvta_generic_to_shared(sh);
        asm volatile("fence.proxy.async.shared::cta;" ::: "memory");
        asm volatile(
            "cp.reduce.async.bulk.global.shared::cta.bulk_group.add.f32 "
            "[%0], [%1], %2;"
            :: "l"(dst), "r"(smem_u32), "r"((int)(FHB * sizeof(float)))
            : "memory");
        asm volatile("cp.async.bulk.commit_group;" ::: "memory");
        asm volatile("cp.async.bulk.wait_group.read 0;" ::: "memory");
    }
}

// Reduce NG copies + parallel scan + finalize; re-zero g_red for next replay.
__global__ void __launch_bounds__(AT) auc_kernel(float* __restrict__ out) {
    __shared__ float sh[FHB];                // reduced: [neg | pos], 4 KB
    __shared__ float s_warp[NW];
    __shared__ float s_wn_warp[NW];
    __shared__ float s_num_warp[NW];
    __shared__ float s_wpos;

    const int task = blockIdx.x;
    const int t    = threadIdx.x;
    const int lane = t & 31;
    const int wid  = t >> 5;

    // ---- reduce NG=4 group copies (1 column/thread); re-zero in place ----
    {
        float4* __restrict__ src =
            reinterpret_cast<float4*>(g_red + (size_t)task * NG * FHB) + t;
        const float4 z = make_float4(0.f, 0.f, 0.f, 0.f);
        float4 s = z;
#pragma unroll
        for (int g = 0; g < NG; g++) {
            const float4 v = src[(size_t)g * COLS4];
            s.x += v.x; s.y += v.y; s.z += v.z; s.w += v.w;
        }
#pragma unroll
        for (int g = 0; g < NG; g++) src[(size_t)g * COLS4] = z;
        reinterpret_cast<float4*>(sh)[t] = s;
    }
    __syncthreads();

    // ---- per-thread sums over PB=2 bins, descending prediction order ----
    const int PB = FB / AT;  // 2
    float swp = 0.0f, swn = 0.0f;
#pragma unroll
    for (int k = 0; k < PB; k++) {
        const int bin = FB - 1 - (t * PB + k);
        swp += sh[FB + bin];
        swn += sh[bin];
    }

    // ---- warp-parallel exclusive prefix of swp across 256 threads ----
    float incl = swp;
#pragma unroll
    for (int d = 1; d < 32; d <<= 1) {
        const float v = __shfl_up_sync(0xffffffffu, incl, d);
        if (lane >= d) incl += v;
    }
    if (lane == 31) s_warp[wid] = incl;          // warp totals
    __syncthreads();
    if (wid == 0) {
        float wv = (lane < NW) ? s_warp[lane] : 0.0f;
        float wincl = wv;
#pragma unroll
        for (int d = 1; d < NW; d <<= 1) {
            const float v = __shfl_up_sync(0xffffffffu, wincl, d);
            if (lane >= d) wincl += v;
        }
        if (lane < NW) s_warp[lane] = wincl - wv;    // exclusive warp offsets
        if (lane == NW - 1) s_wpos = wincl;          // total W_pos
    }
    __syncthreads();
    const float pref = s_warp[wid] + (incl - swp);   // exclusive prefix for t

    // ---- numerator for this thread's bins ----
    float cum = pref;    // positive weight strictly above these bins
    float num = 0.0f;
#pragma unroll
    for (int k = 0; k < PB; k++) {
        const int bin = FB - 1 - (t * PB + k);
        const float wp = sh[FB + bin];
        const float wn = sh[bin];
        num += wn * (cum + 0.5f * wp);
        cum += wp;
    }

    // ---- tree-reduce num and swn ----
#pragma unroll
    for (int d = 16; d >= 1; d >>= 1) {
        num += __shfl_down_sync(0xffffffffu, num, d);
        swn += __shfl_down_sync(0xffffffffu, swn, d);
    }
    if (lane == 0) { s_num_warp[wid] = num; s_wn_warp[wid] = swn; }
    __syncthreads();

    if (t == 0) {
        float tot = 0.0f, Wn = 0.0f;
#pragma unroll
        for (int i = 0; i < NW; i++) { tot += s_num_warp[i]; Wn += s_wn_warp[i]; }
        const float Wp = s_wpos;
        const double denom = (double)Wp * (double)Wn;
        out[task] = (denom == 0.0) ? 0.5f : (float)((double)tot / denom);
    }
}

extern "C" void kernel_launch(void* const* d_in, const int* in_sizes, int n_in,
                              void* d_out, int out_size) {
    // The three big float arrays in metadata order: predictions, labels, weights.
    const float* pred = nullptr;
    const float* lab  = nullptr;
    const float* wt   = nullptr;
    int found = 0;
    for (int i = 0; i < n_in; i++) {
        if (in_sizes[i] == N_TASKS * N_EX) {
            if      (found == 0) pred = (const float*)d_in[i];
            else if (found == 1) lab  = (const float*)d_in[i];
            else if (found == 2) wt   = (const float*)d_in[i];
            found++;
        }
    }

    dim3 grid(NCHUNK, N_TASKS);  // 1024 CTAs, 8/SM -> one full wave
    hist_kernel<<<grid, HT>>>(pred, lab, wt);
    auc_kernel<<<N_TASKS, AT>>>((float*)d_out);
}